// round 9
// baseline (speedup 1.0000x reference)
#include <cuda_runtime.h>
#include <cuda_bf16.h>
#include <cstdint>

// ---------------- problem constants ----------------
#define NB 64
#define NS 1024
#define NH 512
#define NM (NB*NS)          // 65536 rows
#define NN 512
#define WSTRIDE (512*512)
#define PLANE ((size_t)NM*NN)

// GEMM tiling: BM=BN=128, 8 warps (2x4), warp tile 64x32.
// Super-iteration: one K=32 chunk, 4 tiles (Ahi,Alo,Bhi,Blo), split hi/lo commit groups.
#define BM 128
#define BN 128
#define BK 32
#define NSUP 16             // 512 / 32
#define ROWB 80             // 64B data + 16B pad: 16B-aligned rows, conflict-free
#define TILE_B (128*ROWB)   // 10240
#define SLOT (4*TILE_B)     // 40960
#define SMEM_BYTES (2*SLOT) // 81920 -> 2 CTAs/SM

#define A_HI_OFF 0
#define A_LO_OFF TILE_B
#define B_HI_OFF (2*TILE_B)
#define B_LO_OFF (3*TILE_B)

// ---------------- device scratch ----------------
__device__ __nv_bfloat16 g_act_hi[(size_t)5*NM*NN];  // 0=X 1=rh 2=h0 3=h1 4=h2
__device__ __nv_bfloat16 g_act_lo[(size_t)5*NM*NN];
__device__ __nv_bfloat16 g_wt_hi[(size_t)13*WSTRIDE]; // B^T [N,K] per slot
__device__ __nv_bfloat16 g_wt_lo[(size_t)13*WSTRIDE];
__device__ float g_z [PLANE];
__device__ float g_ag[PLANE];
__device__ float g_hz [NB*NH];
__device__ float g_hr [NB*NH];
__device__ float g_h0c[NB*NH];

// ---------------- helpers ----------------
__device__ __forceinline__ uint32_t smem_u32(const void* p) {
    uint32_t a;
    asm("{ .reg .u64 t; cvta.to.shared.u64 t, %1; cvt.u32.u64 %0, t; }" : "=r"(a) : "l"(p));
    return a;
}
__device__ __forceinline__ void cp_async16(uint32_t dst, const void* src) {
    asm volatile("cp.async.cg.shared.global [%0], [%1], 16;" :: "r"(dst), "l"(src) : "memory");
}
__device__ __forceinline__ void cp_commit() { asm volatile("cp.async.commit_group;" ::: "memory"); }
template<int N>
__device__ __forceinline__ void cp_wait() { asm volatile("cp.async.wait_group %0;" :: "n"(N) : "memory"); }
__device__ __forceinline__ void ldmatrix4(uint32_t& r0, uint32_t& r1, uint32_t& r2, uint32_t& r3, uint32_t addr) {
    asm volatile("ldmatrix.sync.aligned.m8n8.x4.shared.b16 {%0,%1,%2,%3}, [%4];"
                 : "=r"(r0), "=r"(r1), "=r"(r2), "=r"(r3) : "r"(addr));
}
__device__ __forceinline__ void mma_bf16(float* d, const uint32_t* a, const uint32_t* b) {
    asm volatile("mma.sync.aligned.m16n8k16.row.col.f32.bf16.bf16.f32 "
        "{%0,%1,%2,%3}, {%4,%5,%6,%7}, {%8,%9}, {%0,%1,%2,%3};"
        : "+f"(d[0]), "+f"(d[1]), "+f"(d[2]), "+f"(d[3])
        : "r"(a[0]), "r"(a[1]), "r"(a[2]), "r"(a[3]), "r"(b[0]), "r"(b[1]));
}
__device__ __forceinline__ void split2(float v, __nv_bfloat16& hi, __nv_bfloat16& lo) {
    hi = __float2bfloat16(v);
    lo = __float2bfloat16(v - __bfloat162float(hi));
}

// ---------------- prep kernels ----------------
__global__ void k_split(const float4* __restrict__ x,
                        __nv_bfloat16* __restrict__ hi, __nv_bfloat16* __restrict__ lo) {
    size_t i = (size_t)blockIdx.x * blockDim.x + threadIdx.x;
    float4 v = x[i];
    float a[4] = {v.x, v.y, v.z, v.w};
    #pragma unroll
    for (int j = 0; j < 4; j++) {
        __nv_bfloat16 h, l; split2(a[j], h, l);
        hi[4*i + j] = h; lo[4*i + j] = l;
    }
}

// All 13 weight-prep jobs in one launch.
__global__ void k_wprep_all(
    const float* __restrict__ Wzx, const float* __restrict__ Wzh,
    const float* __restrict__ Wrx, const float* __restrict__ Wrh,
    const float* __restrict__ Wgx, const float* __restrict__ Wgh,
    const float* __restrict__ Wout,
    __nv_bfloat16* __restrict__ whi, __nv_bfloat16* __restrict__ wlo)
{
    const int j = blockIdx.z;
    const size_t WS = (size_t)WSTRIDE;
    const float *W, *W2 = nullptr;
    if (j == 12) {
        W = Wout;
    } else {
        int l = j >> 2, s = j & 3;
        if (s == 0)      { W = Wzx + l*WS; W2 = l ? (Wzh + l*WS) : nullptr; }
        else if (s == 1) { W = Wrx + l*WS; W2 = l ? (Wrh + l*WS) : nullptr; }
        else if (s == 2) { W = Wgx + l*WS; }
        else             { W = Wgh + l*WS; }
    }
    __nv_bfloat16* hi = whi + (size_t)j * WS;
    __nv_bfloat16* lo = wlo + (size_t)j * WS;
    __shared__ float t[32][33];
    int k0 = blockIdx.y * 32, n0 = blockIdx.x * 32;
    for (int r = threadIdx.y; r < 32; r += 8) {
        float v = W[(size_t)(k0 + r) * 512 + n0 + threadIdx.x];
        if (W2) v += W2[(size_t)(k0 + r) * 512 + n0 + threadIdx.x];
        t[r][threadIdx.x] = v;
    }
    __syncthreads();
    for (int r = threadIdx.y; r < 32; r += 8) {
        float v = t[threadIdx.x][r];
        __nv_bfloat16 h, l; split2(v, h, l);
        hi[(size_t)(n0 + r) * 512 + k0 + threadIdx.x] = h;
        lo[(size_t)(n0 + r) * 512 + k0 + threadIdx.x] = l;
    }
}

__global__ void k_pre(const float* __restrict__ hs,
                      const float* __restrict__ Wzh0, const float* __restrict__ Wrh0,
                      float* __restrict__ hz, float* __restrict__ hr, float* __restrict__ h0c) {
    __shared__ float h0s[512];
    int b = blockIdx.x, n = threadIdx.x;
    float h0v = hs[b*3*NH + n];
    h0s[n] = h0v;
    if (blockIdx.y == 0) h0c[b*NH + n] = h0v;
    __syncthreads();
    const float* W = blockIdx.y ? Wrh0 : Wzh0;
    float acc = 0.f;
    #pragma unroll 8
    for (int k = 0; k < 512; k++) acc = fmaf(h0s[k], W[k*512 + n], acc);
    (blockIdx.y ? hr : hz)[b*NH + n] = acc;
}

__global__ void k_tail(const float* __restrict__ hs,
                       const __nv_bfloat16* __restrict__ h0hi, const __nv_bfloat16* __restrict__ h0lo,
                       const __nv_bfloat16* __restrict__ h1hi, const __nv_bfloat16* __restrict__ h1lo,
                       float* __restrict__ out_h) {
    int b = blockIdx.x, n = threadIdx.x;
    size_t last = ((size_t)b*NS + (NS-1)) * (size_t)NN + n;
    out_h[b*3*NH + n]        = hs[b*3*NH + n];
    out_h[b*3*NH + 512 + n]  = __bfloat162float(h0hi[last]) + __bfloat162float(h0lo[last]);
    out_h[b*3*NH + 1024 + n] = __bfloat162float(h1hi[last]) + __bfloat162float(h1lo[last]);
}

// ---------------- bf16x3 HMMA GEMM, split hi/lo staged pipeline ----------------
// C = Ahi@Bhi^T + Ahi@Blo^T + Alo@Bhi^T, K=512, 16 super-iters of K=32.
template<int EPI>
__global__ void __launch_bounds__(256, 2) gemm_mma(
    const __nv_bfloat16* __restrict__ Ahi, const __nv_bfloat16* __restrict__ Alo,
    const __nv_bfloat16* __restrict__ Bhi, const __nv_bfloat16* __restrict__ Blo,
    float* __restrict__ Cf,
    __nv_bfloat16* __restrict__ Chi, __nv_bfloat16* __restrict__ Clo,
    const float* __restrict__ bias, const float* __restrict__ hterm,
    const float* __restrict__ h0c,
    const __nv_bfloat16* __restrict__ hvhi, const __nv_bfloat16* __restrict__ hvlo,
    const float* __restrict__ zb, const float* __restrict__ agb)
{
    extern __shared__ char smem_raw[];
    const uint32_t base = smem_u32(smem_raw);
    const int tid = threadIdx.x;
    const int lane = tid & 31;
    const int w = tid >> 5;
    const int wr = w >> 2;          // 0..1 (64 rows)
    const int wc = w & 3;           // 0..3 (32 cols)
    const int bm = blockIdx.y * BM;
    const int bn = blockIdx.x * BN;

    float c[4][4][4];
    #pragma unroll
    for (int i = 0; i < 4; i++)
        #pragma unroll
        for (int j = 0; j < 4; j++)
            #pragma unroll
            for (int e = 0; e < 4; e++) c[i][j][e] = 0.f;

    // per-lane ldmatrix byte offsets within a tile (rows 16B-aligned)
    const uint32_t a_lm = (wr*64 + ((lane>>3)&1)*8 + (lane&7)) * ROWB + (lane>>4)*16;
    const uint32_t b_lm = (wc*32 + (lane>>4)*8 + (lane&7)) * ROWB + ((lane>>3)&1)*16;

    // copy mapping: per tile 128 rows x 4 16B-chunks = 512 chunks; 2 tiles/group -> 4 cp/thread
    const int crow = tid >> 2;        // 0..63
    const int ccs  = (tid & 3) * 16;  // byte offset of 16B chunk in row
    auto issue_hi = [&](int s) {
        const int kk = s * BK + (ccs >> 1);
        const uint32_t sb = base + (s & 1) * SLOT;
        #pragma unroll
        for (int i = 0; i < 2; i++) {
            const int row = crow + i * 64;
            const uint32_t so = row * ROWB + ccs;
            cp_async16(sb + A_HI_OFF + so, Ahi + (size_t)(bm + row) * 512 + kk);
            cp_async16(sb + B_HI_OFF + so, Bhi + (size_t)(bn + row) * 512 + kk);
        }
    };
    auto issue_lo = [&](int s) {
        const int kk = s * BK + (ccs >> 1);
        const uint32_t sb = base + (s & 1) * SLOT;
        #pragma unroll
        for (int i = 0; i < 2; i++) {
            const int row = crow + i * 64;
            const uint32_t so = row * ROWB + ccs;
            cp_async16(sb + A_LO_OFF + so, Alo + (size_t)(bm + row) * 512 + kk);
            cp_async16(sb + B_LO_OFF + so, Blo + (size_t)(bn + row) * 512 + kk);
        }
    };

    issue_hi(0); cp_commit();
    issue_lo(0); cp_commit();

    for (int s = 0; s < NSUP; s++) {
        // pending (oldest first): [Ghi(s), Glo(s)]
        cp_wait<1>();                    // Ghi(s) resident
        __syncthreads();                 // prev compute done + hi visibility
        if (s + 1 < NSUP) {
            issue_hi(s + 1); cp_commit();
            issue_lo(s + 1); cp_commit();
        }

        const uint32_t sb = base + (s & 1) * SLOT;

        // ---- Phase A: hh for both kh (covers Glo flight) ----
        #pragma unroll
        for (int kh = 0; kh < 2; kh++) {
            const uint32_t ko = kh * 32;
            uint32_t ah[4][4], bh[4][2];
            #pragma unroll
            for (int mt = 0; mt < 4; mt++)
                ldmatrix4(ah[mt][0], ah[mt][1], ah[mt][2], ah[mt][3],
                          sb + A_HI_OFF + a_lm + mt * (16*ROWB) + ko);
            #pragma unroll
            for (int np = 0; np < 2; np++) {
                uint32_t r0, r1, r2, r3;
                ldmatrix4(r0, r1, r2, r3, sb + B_HI_OFF + b_lm + np * (16*ROWB) + ko);
                bh[np*2][0] = r0;   bh[np*2][1] = r1;
                bh[np*2+1][0] = r2; bh[np*2+1][1] = r3;
            }
            #pragma unroll
            for (int mt = 0; mt < 4; mt++)
                #pragma unroll
                for (int nt = 0; nt < 4; nt++)
                    mma_bf16(c[mt][nt], ah[mt], bh[nt]);
        }

        // ---- Glo(s) arrival + visibility ----
        if (s + 1 < NSUP) cp_wait<2>(); else cp_wait<0>();
        __syncthreads();

        // ---- Phase B: hl then lh (reload ah/bh per kh) ----
        #pragma unroll
        for (int kh = 0; kh < 2; kh++) {
            const uint32_t ko = kh * 32;
            uint32_t ax[4][4], bx[4][2];
            // hl: Ahi x Blo
            #pragma unroll
            for (int mt = 0; mt < 4; mt++)
                ldmatrix4(ax[mt][0], ax[mt][1], ax[mt][2], ax[mt][3],
                          sb + A_HI_OFF + a_lm + mt * (16*ROWB) + ko);
            #pragma unroll
            for (int np = 0; np < 2; np++) {
                uint32_t r0, r1, r2, r3;
                ldmatrix4(r0, r1, r2, r3, sb + B_LO_OFF + b_lm + np * (16*ROWB) + ko);
                bx[np*2][0] = r0;   bx[np*2][1] = r1;
                bx[np*2+1][0] = r2; bx[np*2+1][1] = r3;
            }
            #pragma unroll
            for (int mt = 0; mt < 4; mt++)
                #pragma unroll
                for (int nt = 0; nt < 4; nt++)
                    mma_bf16(c[mt][nt], ax[mt], bx[nt]);
            // lh: Alo x Bhi
            #pragma unroll
            for (int mt = 0; mt < 4; mt++)
                ldmatrix4(ax[mt][0], ax[mt][1], ax[mt][2], ax[mt][3],
                          sb + A_LO_OFF + a_lm + mt * (16*ROWB) + ko);
            #pragma unroll
            for (int np = 0; np < 2; np++) {
                uint32_t r0, r1, r2, r3;
                ldmatrix4(r0, r1, r2, r3, sb + B_HI_OFF + b_lm + np * (16*ROWB) + ko);
                bx[np*2][0] = r0;   bx[np*2][1] = r1;
                bx[np*2+1][0] = r2; bx[np*2+1][1] = r3;
            }
            #pragma unroll
            for (int mt = 0; mt < 4; mt++)
                #pragma unroll
                for (int nt = 0; nt < 4; nt++)
                    mma_bf16(c[mt][nt], ax[mt], bx[nt]);
        }
    }

    // ---- fused epilogue (registers only) ----
    const int rbase = bm + wr * 64;
    const int cbase = bn + wc * 32;
    #pragma unroll
    for (int mt = 0; mt < 4; mt++) {
        #pragma unroll
        for (int er = 0; er < 2; er++) {
            const int gm = rbase + mt*16 + (lane >> 2) + er*8;
            const int bb = gm >> 10;
            #pragma unroll
            for (int nt = 0; nt < 4; nt++) {
                #pragma unroll
                for (int ec = 0; ec < 2; ec++) {
                    const int gn = cbase + nt*8 + (lane & 3)*2 + ec;
                    const size_t idx = (size_t)gm * NN + gn;
                    float v = c[mt][nt][er*2 + ec];
                    if (EPI == 1) {
                        v += bias[gn];
                        if (hterm) v += hterm[bb * NH + gn];
                        Cf[idx] = 1.f / (1.f + __expf(-v));
                    } else if (EPI == 2) {
                        v += bias[gn];
                        if (hterm) v += hterm[bb * NH + gn];
                        float r_ = 1.f / (1.f + __expf(-v));
                        float hv = h0c ? h0c[bb * NH + gn]
                                       : __bfloat162float(hvhi[idx]) + __bfloat162float(hvlo[idx]);
                        float o = r_ * hv;
                        __nv_bfloat16 h, l; split2(o, h, l);
                        Chi[idx] = h; Clo[idx] = l;
                    } else if (EPI == 3) {
                        Cf[idx] = v + (bias ? bias[gn] : 0.f);
                    } else {
                        float g = tanhf(v + agb[idx]);
                        float z = zb[idx];
                        float hv = h0c ? h0c[bb * NH + gn]
                                       : __bfloat162float(hvhi[idx]) + __bfloat162float(hvlo[idx]);
                        float o = z * hv + (1.f - z) * g;
                        __nv_bfloat16 h, l; split2(o, h, l);
                        Chi[idx] = h; Clo[idx] = l;
                    }
                }
            }
        }
    }
}

// ---------------- host ----------------
extern "C" void kernel_launch(void* const* d_in, const int* in_sizes, int n_in,
                              void* d_out, int out_size) {
    const float* input = (const float*)d_in[0];
    const float* hs    = (const float*)d_in[1];
    const float* Wzx   = (const float*)d_in[2];
    const float* bzx   = (const float*)d_in[3];
    const float* Wzh   = (const float*)d_in[4];
    const float* Wrx   = (const float*)d_in[5];
    const float* brx   = (const float*)d_in[6];
    const float* Wrh   = (const float*)d_in[7];
    const float* Wgx   = (const float*)d_in[8];
    const float* bgx   = (const float*)d_in[9];
    const float* Wgh   = (const float*)d_in[10];
    const float* Wout  = (const float*)d_in[11];
    const float* bout  = (const float*)d_in[12];
    float* out = (float*)d_out;

    __nv_bfloat16 *ahi, *alo, *whi, *wlo;
    float *z, *ag, *hz, *hr, *h0c;
    cudaGetSymbolAddress((void**)&ahi, g_act_hi);
    cudaGetSymbolAddress((void**)&alo, g_act_lo);
    cudaGetSymbolAddress((void**)&whi, g_wt_hi);
    cudaGetSymbolAddress((void**)&wlo, g_wt_lo);
    cudaGetSymbolAddress((void**)&z,   g_z);
    cudaGetSymbolAddress((void**)&ag,  g_ag);
    cudaGetSymbolAddress((void**)&hz,  g_hz);
    cudaGetSymbolAddress((void**)&hr,  g_hr);
    cudaGetSymbolAddress((void**)&h0c, g_h0c);

    cudaFuncSetAttribute(gemm_mma<1>, cudaFuncAttributeMaxDynamicSharedMemorySize, SMEM_BYTES);
    cudaFuncSetAttribute(gemm_mma<2>, cudaFuncAttributeMaxDynamicSharedMemorySize, SMEM_BYTES);
    cudaFuncSetAttribute(gemm_mma<3>, cudaFuncAttributeMaxDynamicSharedMemorySize, SMEM_BYTES);
    cudaFuncSetAttribute(gemm_mma<4>, cudaFuncAttributeMaxDynamicSharedMemorySize, SMEM_BYTES);

    // ---- prep ----
    k_split<<<PLANE/4/256, 256>>>((const float4*)input, ahi, alo);
    k_pre<<<dim3(64,2), 512>>>(hs, Wzh, Wrh, hz, hr, h0c);
    k_wprep_all<<<dim3(16,16,13), dim3(32,8)>>>(Wzx, Wzh, Wrx, Wrh, Wgx, Wgh, Wout, whi, wlo);

    dim3 grid(NN / BN, NM / BM);   // (4, 512)
    dim3 blk(256);
    __nv_bfloat16* AH[5]; __nv_bfloat16* AL[5];
    for (int i = 0; i < 5; i++) { AH[i] = ahi + (size_t)i*PLANE; AL[i] = alo + (size_t)i*PLANE; }
    #define WSLOT(s) (whi + (size_t)(s)*WSTRIDE), (wlo + (size_t)(s)*WSTRIDE)

    // ---- layer 0 (h = const h0; x = input, plane 0) ----
    gemm_mma<1><<<grid,blk,SMEM_BYTES>>>(AH[0],AL[0], WSLOT(0),  z,  nullptr,nullptr, bzx,      hz,  nullptr, nullptr,nullptr, nullptr,nullptr);
    gemm_mma<2><<<grid,blk,SMEM_BYTES>>>(AH[0],AL[0], WSLOT(1),  nullptr, AH[1],AL[1], brx,     hr,  h0c,     nullptr,nullptr, nullptr,nullptr);
    gemm_mma<3><<<grid,blk,SMEM_BYTES>>>(AH[0],AL[0], WSLOT(2),  ag, nullptr,nullptr, bgx,      nullptr,nullptr, nullptr,nullptr, nullptr,nullptr);
    gemm_mma<4><<<grid,blk,SMEM_BYTES>>>(AH[1],AL[1], WSLOT(3),  nullptr, AH[2],AL[2], nullptr, nullptr, h0c, nullptr,nullptr, z, ag);
    // ---- layer 1 (x == h == plane 2) ----
    gemm_mma<1><<<grid,blk,SMEM_BYTES>>>(AH[2],AL[2], WSLOT(4),  z,  nullptr,nullptr, bzx+512,  nullptr,nullptr, nullptr,nullptr, nullptr,nullptr);
    gemm_mma<2><<<grid,blk,SMEM_BYTES>>>(AH[2],AL[2], WSLOT(5),  nullptr, AH[1],AL[1], brx+512, nullptr, nullptr, AH[2],AL[2], nullptr,nullptr);
    gemm_mma<3><<<grid,blk,SMEM_BYTES>>>(AH[2],AL[2], WSLOT(6),  ag, nullptr,nullptr, bgx+512,  nullptr,nullptr, nullptr,nullptr, nullptr,nullptr);
    gemm_mma<4><<<grid,blk,SMEM_BYTES>>>(AH[1],AL[1], WSLOT(7),  nullptr, AH[3],AL[3], nullptr, nullptr, nullptr, AH[2],AL[2], z, ag);
    // ---- layer 2 (x == h == plane 3) ----
    gemm_mma<1><<<grid,blk,SMEM_BYTES>>>(AH[3],AL[3], WSLOT(8),  z,  nullptr,nullptr, bzx+1024, nullptr,nullptr, nullptr,nullptr, nullptr,nullptr);
    gemm_mma<2><<<grid,blk,SMEM_BYTES>>>(AH[3],AL[3], WSLOT(9),  nullptr, AH[1],AL[1], brx+1024, nullptr, nullptr, AH[3],AL[3], nullptr,nullptr);
    gemm_mma<3><<<grid,blk,SMEM_BYTES>>>(AH[3],AL[3], WSLOT(10), ag, nullptr,nullptr, bgx+1024, nullptr,nullptr, nullptr,nullptr, nullptr,nullptr);
    gemm_mma<4><<<grid,blk,SMEM_BYTES>>>(AH[1],AL[1], WSLOT(11), nullptr, AH[4],AL[4], nullptr, nullptr, nullptr, AH[3],AL[3], z, ag);
    // ---- output projection ----
    gemm_mma<3><<<grid,blk,SMEM_BYTES>>>(AH[4],AL[4], WSLOT(12), out, nullptr,nullptr, bout,    nullptr,nullptr, nullptr,nullptr, nullptr,nullptr);

    k_tail<<<64, 512>>>(hs, AH[2],AL[2], AH[3],AL[3], out + PLANE);
}

// round 10
// speedup vs baseline: 1.2191x; 1.2191x over previous
#include <cuda_runtime.h>
#include <cuda_bf16.h>
#include <cstdint>

// ---------------- problem constants ----------------
#define NB 64
#define NS 1024
#define NH 512
#define NM (NB*NS)          // 65536 rows
#define NN 512
#define WSTRIDE (512*512)
#define PLANE ((size_t)NM*NN)

// GEMM tiling: BM=BN=128, 8 warps (2x4), warp tile 64x32.
// Super-iteration: one K=32 chunk, 4 tiles (Ahi,Alo,Bhi,Blo), 96 mmas.
// SW64 swizzle, no padding: ROWB=64. 3 slots -> prefetch depth 2.
#define BM 128
#define BN 128
#define BK 32
#define NSUP 16             // 512 / 32
#define ROWB 64             // one K=32 bf16 chunk per row, swizzled (no pad)
#define TILE_B (128*ROWB)   // 8192
#define SLOT (4*TILE_B)     // 32768
#define SMEM_BYTES (3*SLOT) // 98304 -> 2 CTAs/SM

#define A_HI_OFF 0
#define A_LO_OFF TILE_B
#define B_HI_OFF (2*TILE_B)
#define B_LO_OFF (3*TILE_B)

// ---------------- device scratch ----------------
__device__ __nv_bfloat16 g_act_hi[(size_t)5*NM*NN];  // 0=X 1=rh 2=h0 3=h1 4=h2
__device__ __nv_bfloat16 g_act_lo[(size_t)5*NM*NN];
__device__ __nv_bfloat16 g_wt_hi[(size_t)13*WSTRIDE]; // B^T [N,K] per slot
__device__ __nv_bfloat16 g_wt_lo[(size_t)13*WSTRIDE];
__device__ float g_z [PLANE];
__device__ float g_ag[PLANE];
__device__ float g_hz [NB*NH];
__device__ float g_hr [NB*NH];
__device__ float g_h0c[NB*NH];

// ---------------- helpers ----------------
__device__ __forceinline__ uint32_t smem_u32(const void* p) {
    uint32_t a;
    asm("{ .reg .u64 t; cvta.to.shared.u64 t, %1; cvt.u32.u64 %0, t; }" : "=r"(a) : "l"(p));
    return a;
}
__device__ __forceinline__ void cp_async16(uint32_t dst, const void* src) {
    asm volatile("cp.async.cg.shared.global [%0], [%1], 16;" :: "r"(dst), "l"(src) : "memory");
}
__device__ __forceinline__ void cp_commit() { asm volatile("cp.async.commit_group;" ::: "memory"); }
template<int N>
__device__ __forceinline__ void cp_wait() { asm volatile("cp.async.wait_group %0;" :: "n"(N) : "memory"); }
__device__ __forceinline__ void ldmatrix4(uint32_t& r0, uint32_t& r1, uint32_t& r2, uint32_t& r3, uint32_t addr) {
    asm volatile("ldmatrix.sync.aligned.m8n8.x4.shared.b16 {%0,%1,%2,%3}, [%4];"
                 : "=r"(r0), "=r"(r1), "=r"(r2), "=r"(r3) : "r"(addr));
}
__device__ __forceinline__ void mma_bf16(float* d, const uint32_t* a, const uint32_t* b) {
    asm volatile("mma.sync.aligned.m16n8k16.row.col.f32.bf16.bf16.f32 "
        "{%0,%1,%2,%3}, {%4,%5,%6,%7}, {%8,%9}, {%0,%1,%2,%3};"
        : "+f"(d[0]), "+f"(d[1]), "+f"(d[2]), "+f"(d[3])
        : "r"(a[0]), "r"(a[1]), "r"(a[2]), "r"(a[3]), "r"(b[0]), "r"(b[1]));
}
__device__ __forceinline__ void split2(float v, __nv_bfloat16& hi, __nv_bfloat16& lo) {
    hi = __float2bfloat16(v);
    lo = __float2bfloat16(v - __bfloat162float(hi));
}

// ---------------- prep kernels ----------------
__global__ void k_split(const float4* __restrict__ x,
                        __nv_bfloat16* __restrict__ hi, __nv_bfloat16* __restrict__ lo) {
    size_t i = (size_t)blockIdx.x * blockDim.x + threadIdx.x;
    float4 v = x[i];
    float a[4] = {v.x, v.y, v.z, v.w};
    #pragma unroll
    for (int j = 0; j < 4; j++) {
        __nv_bfloat16 h, l; split2(a[j], h, l);
        hi[4*i + j] = h; lo[4*i + j] = l;
    }
}

// All 13 weight-prep jobs in one launch.
__global__ void k_wprep_all(
    const float* __restrict__ Wzx, const float* __restrict__ Wzh,
    const float* __restrict__ Wrx, const float* __restrict__ Wrh,
    const float* __restrict__ Wgx, const float* __restrict__ Wgh,
    const float* __restrict__ Wout,
    __nv_bfloat16* __restrict__ whi, __nv_bfloat16* __restrict__ wlo)
{
    const int j = blockIdx.z;
    const size_t WS = (size_t)WSTRIDE;
    const float *W, *W2 = nullptr;
    if (j == 12) {
        W = Wout;
    } else {
        int l = j >> 2, s = j & 3;
        if (s == 0)      { W = Wzx + l*WS; W2 = l ? (Wzh + l*WS) : nullptr; }
        else if (s == 1) { W = Wrx + l*WS; W2 = l ? (Wrh + l*WS) : nullptr; }
        else if (s == 2) { W = Wgx + l*WS; }
        else             { W = Wgh + l*WS; }
    }
    __nv_bfloat16* hi = whi + (size_t)j * WS;
    __nv_bfloat16* lo = wlo + (size_t)j * WS;
    __shared__ float t[32][33];
    int k0 = blockIdx.y * 32, n0 = blockIdx.x * 32;
    for (int r = threadIdx.y; r < 32; r += 8) {
        float v = W[(size_t)(k0 + r) * 512 + n0 + threadIdx.x];
        if (W2) v += W2[(size_t)(k0 + r) * 512 + n0 + threadIdx.x];
        t[r][threadIdx.x] = v;
    }
    __syncthreads();
    for (int r = threadIdx.y; r < 32; r += 8) {
        float v = t[threadIdx.x][r];
        __nv_bfloat16 h, l; split2(v, h, l);
        hi[(size_t)(n0 + r) * 512 + k0 + threadIdx.x] = h;
        lo[(size_t)(n0 + r) * 512 + k0 + threadIdx.x] = l;
    }
}

__global__ void k_pre(const float* __restrict__ hs,
                      const float* __restrict__ Wzh0, const float* __restrict__ Wrh0,
                      float* __restrict__ hz, float* __restrict__ hr, float* __restrict__ h0c) {
    __shared__ float h0s[512];
    int b = blockIdx.x, n = threadIdx.x;
    float h0v = hs[b*3*NH + n];
    h0s[n] = h0v;
    if (blockIdx.y == 0) h0c[b*NH + n] = h0v;
    __syncthreads();
    const float* W = blockIdx.y ? Wrh0 : Wzh0;
    float acc = 0.f;
    #pragma unroll 8
    for (int k = 0; k < 512; k++) acc = fmaf(h0s[k], W[k*512 + n], acc);
    (blockIdx.y ? hr : hz)[b*NH + n] = acc;
}

__global__ void k_tail(const float* __restrict__ hs,
                       const __nv_bfloat16* __restrict__ h0hi, const __nv_bfloat16* __restrict__ h0lo,
                       const __nv_bfloat16* __restrict__ h1hi, const __nv_bfloat16* __restrict__ h1lo,
                       float* __restrict__ out_h) {
    int b = blockIdx.x, n = threadIdx.x;
    size_t last = ((size_t)b*NS + (NS-1)) * (size_t)NN + n;
    out_h[b*3*NH + n]        = hs[b*3*NH + n];
    out_h[b*3*NH + 512 + n]  = __bfloat162float(h0hi[last]) + __bfloat162float(h0lo[last]);
    out_h[b*3*NH + 1024 + n] = __bfloat162float(h1hi[last]) + __bfloat162float(h1lo[last]);
}

// ---------------- bf16x3 HMMA GEMM, SW64-swizzled, depth-2 pipeline ----------------
// C = Ahi@Bhi^T + Ahi@Blo^T + Alo@Bhi^T, K=512, 16 super-iters of K=32.
template<int EPI>
__global__ void __launch_bounds__(256, 2) gemm_mma(
    const __nv_bfloat16* __restrict__ Ahi, const __nv_bfloat16* __restrict__ Alo,
    const __nv_bfloat16* __restrict__ Bhi, const __nv_bfloat16* __restrict__ Blo,
    float* __restrict__ Cf,
    __nv_bfloat16* __restrict__ Chi, __nv_bfloat16* __restrict__ Clo,
    const float* __restrict__ bias, const float* __restrict__ hterm,
    const float* __restrict__ h0c,
    const __nv_bfloat16* __restrict__ hvhi, const __nv_bfloat16* __restrict__ hvlo,
    const float* __restrict__ zb, const float* __restrict__ agb)
{
    extern __shared__ char smem_raw[];
    const uint32_t base = smem_u32(smem_raw);
    const int tid = threadIdx.x;
    const int lane = tid & 31;
    const int w = tid >> 5;
    const int wr = w >> 2;          // 0..1 (64 rows)
    const int wc = w & 3;           // 0..3 (32 cols)
    const int bm = blockIdx.y * BM;
    const int bn = blockIdx.x * BN;

    float c[4][4][4];
    #pragma unroll
    for (int i = 0; i < 4; i++)
        #pragma unroll
        for (int j = 0; j < 4; j++)
            #pragma unroll
            for (int e = 0; e < 4; e++) c[i][j][e] = 0.f;

    // per-lane swizzled ldmatrix offsets. SW64: XOR term = (8*row)&0x30, row-only,
    // invariant under +16/+64 row strides; kh (+32B col) applied as address XOR.
    const int a_row = wr*64 + ((lane>>3)&1)*8 + (lane&7);
    const int a_colb = (lane>>4)*16;
    const uint32_t a_lm = a_row*ROWB + (a_colb ^ ((a_row<<3)&0x30));
    const int b_row = wc*32 + (lane>>4)*8 + (lane&7);
    const int b_colb = ((lane>>3)&1)*16;
    const uint32_t b_lm = b_row*ROWB + (b_colb ^ ((b_row<<3)&0x30));

    // copy: per tile 128 rows x 4 16B-chunks = 512 chunks, 4 tiles -> 8 cp/thread
    const int crow = tid >> 2;                          // 0..63
    const int ccs  = (tid & 3) * 16;                    // chunk byte col in row
    const uint32_t cdc = ccs ^ ((crow<<3)&0x30);        // swizzled col (same for crow+64)
    auto issue = [&](int s) {
        const int kk = s * BK + (ccs >> 1);             // global elem col
        const uint32_t sb = base + (s % 3) * SLOT;
        #pragma unroll
        for (int i = 0; i < 2; i++) {
            const int row = crow + i * 64;
            const uint32_t so = row * ROWB + cdc;
            const size_t ga = (size_t)(bm + row) * 512 + kk;
            const size_t gb = (size_t)(bn + row) * 512 + kk;
            cp_async16(sb + A_HI_OFF + so, Ahi + ga);
            cp_async16(sb + A_LO_OFF + so, Alo + ga);
            cp_async16(sb + B_HI_OFF + so, Bhi + gb);
            cp_async16(sb + B_LO_OFF + so, Blo + gb);
        }
    };

    issue(0); cp_commit();
    issue(1); cp_commit();

    for (int s = 0; s < NSUP; s++) {
        if (s + 1 < NSUP) cp_wait<1>(); else cp_wait<0>();   // slot s resident
        __syncthreads();
        if (s + 2 < NSUP) { issue(s + 2); cp_commit(); }

        const uint32_t sb = base + (s % 3) * SLOT;
        #pragma unroll
        for (int kh = 0; kh < 2; kh++) {
            const uint32_t kx = kh << 5;   // XOR 32 bytes for second half-K
            uint32_t ah[4][4], bh[4][2];
            #pragma unroll
            for (int mt = 0; mt < 4; mt++)
                ldmatrix4(ah[mt][0], ah[mt][1], ah[mt][2], ah[mt][3],
                          (sb + A_HI_OFF + a_lm + mt * (16*ROWB)) ^ kx);
            #pragma unroll
            for (int np = 0; np < 2; np++) {
                uint32_t r0, r1, r2, r3;
                ldmatrix4(r0, r1, r2, r3, (sb + B_HI_OFF + b_lm + np * (16*ROWB)) ^ kx);
                bh[np*2][0] = r0;   bh[np*2][1] = r1;
                bh[np*2+1][0] = r2; bh[np*2+1][1] = r3;
            }
            #pragma unroll
            for (int mt = 0; mt < 4; mt++)
                #pragma unroll
                for (int nt = 0; nt < 4; nt++)
                    mma_bf16(c[mt][nt], ah[mt], bh[nt]);
            {   // hl: Ahi x Blo
                uint32_t bl[4][2];
                #pragma unroll
                for (int np = 0; np < 2; np++) {
                    uint32_t r0, r1, r2, r3;
                    ldmatrix4(r0, r1, r2, r3, (sb + B_LO_OFF + b_lm + np * (16*ROWB)) ^ kx);
                    bl[np*2][0] = r0;   bl[np*2][1] = r1;
                    bl[np*2+1][0] = r2; bl[np*2+1][1] = r3;
                }
                #pragma unroll
                for (int mt = 0; mt < 4; mt++)
                    #pragma unroll
                    for (int nt = 0; nt < 4; nt++)
                        mma_bf16(c[mt][nt], ah[mt], bl[nt]);
            }
            {   // lh: Alo x Bhi
                uint32_t al[4][4];
                #pragma unroll
                for (int mt = 0; mt < 4; mt++)
                    ldmatrix4(al[mt][0], al[mt][1], al[mt][2], al[mt][3],
                              (sb + A_LO_OFF + a_lm + mt * (16*ROWB)) ^ kx);
                #pragma unroll
                for (int mt = 0; mt < 4; mt++)
                    #pragma unroll
                    for (int nt = 0; nt < 4; nt++)
                        mma_bf16(c[mt][nt], al[mt], bh[nt]);
            }
        }
    }

    // ---- fused epilogue (registers only) ----
    const int rbase = bm + wr * 64;
    const int cbase = bn + wc * 32;
    #pragma unroll
    for (int mt = 0; mt < 4; mt++) {
        #pragma unroll
        for (int er = 0; er < 2; er++) {
            const int gm = rbase + mt*16 + (lane >> 2) + er*8;
            const int bb = gm >> 10;
            #pragma unroll
            for (int nt = 0; nt < 4; nt++) {
                #pragma unroll
                for (int ec = 0; ec < 2; ec++) {
                    const int gn = cbase + nt*8 + (lane & 3)*2 + ec;
                    const size_t idx = (size_t)gm * NN + gn;
                    float v = c[mt][nt][er*2 + ec];
                    if (EPI == 1) {
                        v += bias[gn];
                        if (hterm) v += hterm[bb * NH + gn];
                        Cf[idx] = 1.f / (1.f + __expf(-v));
                    } else if (EPI == 2) {
                        v += bias[gn];
                        if (hterm) v += hterm[bb * NH + gn];
                        float r_ = 1.f / (1.f + __expf(-v));
                        float hv = h0c ? h0c[bb * NH + gn]
                                       : __bfloat162float(hvhi[idx]) + __bfloat162float(hvlo[idx]);
                        float o = r_ * hv;
                        __nv_bfloat16 h, l; split2(o, h, l);
                        Chi[idx] = h; Clo[idx] = l;
                    } else if (EPI == 3) {
                        Cf[idx] = v + (bias ? bias[gn] : 0.f);
                    } else {
                        float g = tanhf(v + agb[idx]);
                        float z = zb[idx];
                        float hv = h0c ? h0c[bb * NH + gn]
                                       : __bfloat162float(hvhi[idx]) + __bfloat162float(hvlo[idx]);
                        float o = z * hv + (1.f - z) * g;
                        __nv_bfloat16 h, l; split2(o, h, l);
                        Chi[idx] = h; Clo[idx] = l;
                    }
                }
            }
        }
    }
}

// ---------------- host ----------------
extern "C" void kernel_launch(void* const* d_in, const int* in_sizes, int n_in,
                              void* d_out, int out_size) {
    const float* input = (const float*)d_in[0];
    const float* hs    = (const float*)d_in[1];
    const float* Wzx   = (const float*)d_in[2];
    const float* bzx   = (const float*)d_in[3];
    const float* Wzh   = (const float*)d_in[4];
    const float* Wrx   = (const float*)d_in[5];
    const float* brx   = (const float*)d_in[6];
    const float* Wrh   = (const float*)d_in[7];
    const float* Wgx   = (const float*)d_in[8];
    const float* bgx   = (const float*)d_in[9];
    const float* Wgh   = (const float*)d_in[10];
    const float* Wout  = (const float*)d_in[11];
    const float* bout  = (const float*)d_in[12];
    float* out = (float*)d_out;

    __nv_bfloat16 *ahi, *alo, *whi, *wlo;
    float *z, *ag, *hz, *hr, *h0c;
    cudaGetSymbolAddress((void**)&ahi, g_act_hi);
    cudaGetSymbolAddress((void**)&alo, g_act_lo);
    cudaGetSymbolAddress((void**)&whi, g_wt_hi);
    cudaGetSymbolAddress((void**)&wlo, g_wt_lo);
    cudaGetSymbolAddress((void**)&z,   g_z);
    cudaGetSymbolAddress((void**)&ag,  g_ag);
    cudaGetSymbolAddress((void**)&hz,  g_hz);
    cudaGetSymbolAddress((void**)&hr,  g_hr);
    cudaGetSymbolAddress((void**)&h0c, g_h0c);

    cudaFuncSetAttribute(gemm_mma<1>, cudaFuncAttributeMaxDynamicSharedMemorySize, SMEM_BYTES);
    cudaFuncSetAttribute(gemm_mma<2>, cudaFuncAttributeMaxDynamicSharedMemorySize, SMEM_BYTES);
    cudaFuncSetAttribute(gemm_mma<3>, cudaFuncAttributeMaxDynamicSharedMemorySize, SMEM_BYTES);
    cudaFuncSetAttribute(gemm_mma<4>, cudaFuncAttributeMaxDynamicSharedMemorySize, SMEM_BYTES);

    // ---- prep ----
    k_split<<<PLANE/4/256, 256>>>((const float4*)input, ahi, alo);
    k_pre<<<dim3(64,2), 512>>>(hs, Wzh, Wrh, hz, hr, h0c);
    k_wprep_all<<<dim3(16,16,13), dim3(32,8)>>>(Wzx, Wzh, Wrx, Wrh, Wgx, Wgh, Wout, whi, wlo);

    dim3 grid(NN / BN, NM / BM);   // (4, 512)
    dim3 blk(256);
    __nv_bfloat16* AH[5]; __nv_bfloat16* AL[5];
    for (int i = 0; i < 5; i++) { AH[i] = ahi + (size_t)i*PLANE; AL[i] = alo + (size_t)i*PLANE; }
    #define WSLOT(s) (whi + (size_t)(s)*WSTRIDE), (wlo + (size_t)(s)*WSTRIDE)

    // ---- layer 0 (h = const h0; x = input, plane 0) ----
    gemm_mma<1><<<grid,blk,SMEM_BYTES>>>(AH[0],AL[0], WSLOT(0),  z,  nullptr,nullptr, bzx,      hz,  nullptr, nullptr,nullptr, nullptr,nullptr);
    gemm_mma<2><<<grid,blk,SMEM_BYTES>>>(AH[0],AL[0], WSLOT(1),  nullptr, AH[1],AL[1], brx,     hr,  h0c,     nullptr,nullptr, nullptr,nullptr);
    gemm_mma<3><<<grid,blk,SMEM_BYTES>>>(AH[0],AL[0], WSLOT(2),  ag, nullptr,nullptr, bgx,      nullptr,nullptr, nullptr,nullptr, nullptr,nullptr);
    gemm_mma<4><<<grid,blk,SMEM_BYTES>>>(AH[1],AL[1], WSLOT(3),  nullptr, AH[2],AL[2], nullptr, nullptr, h0c, nullptr,nullptr, z, ag);
    // ---- layer 1 (x == h == plane 2) ----
    gemm_mma<1><<<grid,blk,SMEM_BYTES>>>(AH[2],AL[2], WSLOT(4),  z,  nullptr,nullptr, bzx+512,  nullptr,nullptr, nullptr,nullptr, nullptr,nullptr);
    gemm_mma<2><<<grid,blk,SMEM_BYTES>>>(AH[2],AL[2], WSLOT(5),  nullptr, AH[1],AL[1], brx+512, nullptr, nullptr, AH[2],AL[2], nullptr,nullptr);
    gemm_mma<3><<<grid,blk,SMEM_BYTES>>>(AH[2],AL[2], WSLOT(6),  ag, nullptr,nullptr, bgx+512,  nullptr,nullptr, nullptr,nullptr, nullptr,nullptr);
    gemm_mma<4><<<grid,blk,SMEM_BYTES>>>(AH[1],AL[1], WSLOT(7),  nullptr, AH[3],AL[3], nullptr, nullptr, nullptr, AH[2],AL[2], z, ag);
    // ---- layer 2 (x == h == plane 3) ----
    gemm_mma<1><<<grid,blk,SMEM_BYTES>>>(AH[3],AL[3], WSLOT(8),  z,  nullptr,nullptr, bzx+1024, nullptr,nullptr, nullptr,nullptr, nullptr,nullptr);
    gemm_mma<2><<<grid,blk,SMEM_BYTES>>>(AH[3],AL[3], WSLOT(9),  nullptr, AH[1],AL[1], brx+1024, nullptr, nullptr, AH[3],AL[3], nullptr,nullptr);
    gemm_mma<3><<<grid,blk,SMEM_BYTES>>>(AH[3],AL[3], WSLOT(10), ag, nullptr,nullptr, bgx+1024, nullptr,nullptr, nullptr,nullptr, nullptr,nullptr);
    gemm_mma<4><<<grid,blk,SMEM_BYTES>>>(AH[1],AL[1], WSLOT(11), nullptr, AH[4],AL[4], nullptr, nullptr, nullptr, AH[3],AL[3], z, ag);
    // ---- output projection ----
    gemm_mma<3><<<grid,blk,SMEM_BYTES>>>(AH[4],AL[4], WSLOT(12), out, nullptr,nullptr, bout,    nullptr,nullptr, nullptr,nullptr, nullptr,nullptr);

    k_tail<<<64, 512>>>(hs, AH[2],AL[2], AH[3],AL[3], out + PLANE);
}

// round 11
// speedup vs baseline: 1.5139x; 1.2419x over previous
#include <cuda_runtime.h>
#include <cstdint>

// ---------------- problem constants ----------------
#define NB 64
#define NS 1024
#define NH 512
#define NM (NB*NS)
#define NN 512
#define WSTRIDE (512*512)
#define PLANE ((size_t)NM*NN)

// GEMM tiling: CTA 128x128, 16 warps (4x4), warp tile 32x32, K-chunk 64 (int8).
#define BM 128
#define BN 128
#define KCH 64
#define NSUP 8              // 512 / 64
#define ROWB 64             // bytes per row (64 int8), SW64 swizzle
#define TILE_B (128*ROWB)   // 8192
#define SLOT (4*TILE_B)     // 32768
#define NSLOT 4
#define SMEM_BYTES (NSLOT*SLOT) // 131072 (1 CTA of 512 thr per SM)

#define A_HI_OFF 0
#define A_LO_OFF TILE_B
#define B_HI_OFF (2*TILE_B)
#define B_LO_OFF (3*TILE_B)

// ---------------- device scratch ----------------
__device__ int8_t g_qhi[(size_t)5*PLANE];   // act planes: 0=X 1=rh 2=h0 3=h1 4=h2
__device__ int8_t g_qlo[(size_t)5*PLANE];
__device__ int8_t g_wqh[(size_t)13*WSTRIDE];
__device__ int8_t g_wql[(size_t)13*WSTRIDE];
__device__ float  g_wtf[(size_t)13*WSTRIDE]; // fp32 transposed combined weights
__device__ float  g_sbv[13*512];             // per-row weight scales
__device__ float  g_z [PLANE];
__device__ float  g_ag[PLANE];
__device__ float  g_hz [NB*NH];
__device__ float  g_hr [NB*NH];
__device__ float  g_h0c[NB*NH];
__device__ unsigned g_maxbits[2];            // abs-max bits: [0]=X, [1]=h0(>=1)
__device__ float  g_sc[4];                   // sX, sH, invX, invH

// ---------------- helpers ----------------
__device__ __forceinline__ uint32_t smem_u32(const void* p) {
    uint32_t a;
    asm("{ .reg .u64 t; cvta.to.shared.u64 t, %1; cvt.u32.u64 %0, t; }" : "=r"(a) : "l"(p));
    return a;
}
__device__ __forceinline__ void cp_async16(uint32_t dst, const void* src) {
    asm volatile("cp.async.cg.shared.global [%0], [%1], 16;" :: "r"(dst), "l"(src) : "memory");
}
__device__ __forceinline__ void cp_commit() { asm volatile("cp.async.commit_group;" ::: "memory"); }
template<int N>
__device__ __forceinline__ void cp_wait() { asm volatile("cp.async.wait_group %0;" :: "n"(N) : "memory"); }
__device__ __forceinline__ void ldmatrix4(uint32_t& r0, uint32_t& r1, uint32_t& r2, uint32_t& r3, uint32_t addr) {
    asm volatile("ldmatrix.sync.aligned.m8n8.x4.shared.b16 {%0,%1,%2,%3}, [%4];"
                 : "=r"(r0), "=r"(r1), "=r"(r2), "=r"(r3) : "r"(addr));
}
__device__ __forceinline__ void mma_s8(int* d, const uint32_t* a, const uint32_t* b) {
    asm volatile("mma.sync.aligned.m16n8k32.row.col.s32.s8.s8.s32 "
        "{%0,%1,%2,%3}, {%4,%5,%6,%7}, {%8,%9}, {%0,%1,%2,%3};"
        : "+r"(d[0]), "+r"(d[1]), "+r"(d[2]), "+r"(d[3])
        : "r"(a[0]), "r"(a[1]), "r"(a[2]), "r"(a[3]), "r"(b[0]), "r"(b[1]));
}
__device__ __forceinline__ void quant16(float v, float invS, int8_t* hp, int8_t* lp) {
    int q = __float2int_rn(v * invS);
    q = max(-32512, min(32512, q));
    int h = (q + 128) >> 8;
    *hp = (int8_t)h;
    *lp = (int8_t)(q - (h << 8));
}

// ---------------- prep kernels ----------------
__global__ void k_initmax() {
    g_maxbits[0] = 0u;
    g_maxbits[1] = __float_as_uint(1.0f);   // h bound >= 1 (tanh range)
}
__global__ void k_maxX(const float4* __restrict__ x, size_t n4) {
    __shared__ float red[256];
    float m = 0.f;
    for (size_t i = (size_t)blockIdx.x * blockDim.x + threadIdx.x; i < n4; i += (size_t)gridDim.x * blockDim.x) {
        float4 v = x[i];
        m = fmaxf(m, fmaxf(fmaxf(fabsf(v.x), fabsf(v.y)), fmaxf(fabsf(v.z), fabsf(v.w))));
    }
    red[threadIdx.x] = m;
    __syncthreads();
    for (int s = 128; s > 0; s >>= 1) {
        if (threadIdx.x < s) red[threadIdx.x] = fmaxf(red[threadIdx.x], red[threadIdx.x + s]);
        __syncthreads();
    }
    if (threadIdx.x == 0) atomicMax(&g_maxbits[0], __float_as_uint(red[0]));
}
__global__ void k_maxh0(const float* __restrict__ hs) {
    __shared__ float red[512];
    int b = blockIdx.x, n = threadIdx.x;
    red[n] = fabsf(hs[b*3*NH + n]);
    __syncthreads();
    for (int s = 256; s > 0; s >>= 1) {
        if (n < s) red[n] = fmaxf(red[n], red[n + s]);
        __syncthreads();
    }
    if (n == 0) atomicMax(&g_maxbits[1], __float_as_uint(red[0]));
}
__global__ void k_scale() {
    float mx = fmaxf(__uint_as_float(g_maxbits[0]), 1e-20f);
    float mh = fmaxf(__uint_as_float(g_maxbits[1]), 1e-20f);
    g_sc[0] = mx / 32512.0f;
    g_sc[1] = mh / 32512.0f;
    g_sc[2] = 32512.0f / mx;
    g_sc[3] = 32512.0f / mh;
}
__global__ void k_quantX(const float* __restrict__ x, int8_t* __restrict__ hi, int8_t* __restrict__ lo) {
    float invX = g_sc[2];
    for (size_t i = (size_t)blockIdx.x * blockDim.x + threadIdx.x; i < PLANE; i += (size_t)gridDim.x * blockDim.x)
        quant16(x[i], invX, &hi[i], &lo[i]);
}

// fp32 transpose + optional add -> g_wtf[j][n][k]
__global__ void k_wprep_all(
    const float* __restrict__ Wzx, const float* __restrict__ Wzh,
    const float* __restrict__ Wrx, const float* __restrict__ Wrh,
    const float* __restrict__ Wgx, const float* __restrict__ Wgh,
    const float* __restrict__ Wout, float* __restrict__ wtf)
{
    const int j = blockIdx.z;
    const size_t WS = (size_t)WSTRIDE;
    const float *W, *W2 = nullptr;
    if (j == 12) {
        W = Wout;
    } else {
        int l = j >> 2, s = j & 3;
        if (s == 0)      { W = Wzx + l*WS; W2 = l ? (Wzh + l*WS) : nullptr; }
        else if (s == 1) { W = Wrx + l*WS; W2 = l ? (Wrh + l*WS) : nullptr; }
        else if (s == 2) { W = Wgx + l*WS; }
        else             { W = Wgh + l*WS; }
    }
    float* dst = wtf + (size_t)j * WS;
    __shared__ float t[32][33];
    int k0 = blockIdx.y * 32, n0 = blockIdx.x * 32;
    for (int r = threadIdx.y; r < 32; r += 8) {
        float v = W[(size_t)(k0 + r) * 512 + n0 + threadIdx.x];
        if (W2) v += W2[(size_t)(k0 + r) * 512 + n0 + threadIdx.x];
        t[r][threadIdx.x] = v;
    }
    __syncthreads();
    for (int r = threadIdx.y; r < 32; r += 8)
        dst[(size_t)(n0 + r) * 512 + k0 + threadIdx.x] = t[threadIdx.x][r];
}

// per-row quantization of weights: block = one (slot, row n)
__global__ void k_wquant(const float* __restrict__ wtf,
                         int8_t* __restrict__ wh, int8_t* __restrict__ wl,
                         float* __restrict__ sbv)
{
    __shared__ float red[128];
    const int n = blockIdx.x, j = blockIdx.y, t = threadIdx.x;
    const float* row = wtf + (size_t)j * WSTRIDE + (size_t)n * 512;
    float v0 = row[t], v1 = row[t+128], v2 = row[t+256], v3 = row[t+384];
    float m = fmaxf(fmaxf(fabsf(v0), fabsf(v1)), fmaxf(fabsf(v2), fabsf(v3)));
    red[t] = m;
    __syncthreads();
    for (int s = 64; s > 0; s >>= 1) {
        if (t < s) red[t] = fmaxf(red[t], red[t + s]);
        __syncthreads();
    }
    float mx = fmaxf(red[0], 1e-20f);
    float invS = 32512.0f / mx;
    int8_t* dh = wh + (size_t)j * WSTRIDE + (size_t)n * 512;
    int8_t* dl = wl + (size_t)j * WSTRIDE + (size_t)n * 512;
    quant16(v0, invS, dh + t,       dl + t);
    quant16(v1, invS, dh + t + 128, dl + t + 128);
    quant16(v2, invS, dh + t + 256, dl + t + 256);
    quant16(v3, invS, dh + t + 384, dl + t + 384);
    if (t == 0) sbv[j * 512 + n] = mx / 32512.0f;
}

__global__ void k_pre(const float* __restrict__ hs,
                      const float* __restrict__ Wzh0, const float* __restrict__ Wrh0,
                      float* __restrict__ hz, float* __restrict__ hr, float* __restrict__ h0c) {
    __shared__ float h0s[512];
    int b = blockIdx.x, n = threadIdx.x;
    float h0v = hs[b*3*NH + n];
    h0s[n] = h0v;
    if (blockIdx.y == 0) h0c[b*NH + n] = h0v;
    __syncthreads();
    const float* W = blockIdx.y ? Wrh0 : Wzh0;
    float acc = 0.f;
    #pragma unroll 8
    for (int k = 0; k < 512; k++) acc = fmaf(h0s[k], W[k*512 + n], acc);
    (blockIdx.y ? hr : hz)[b*NH + n] = acc;
}

__global__ void k_tail(const float* __restrict__ hs,
                       const int8_t* __restrict__ h0h, const int8_t* __restrict__ h0l,
                       const int8_t* __restrict__ h1h, const int8_t* __restrict__ h1l,
                       float* __restrict__ out_h) {
    int b = blockIdx.x, n = threadIdx.x;
    float sH = g_sc[1];
    size_t last = ((size_t)b*NS + (NS-1)) * (size_t)NN + n;
    out_h[b*3*NH + n]        = hs[b*3*NH + n];
    out_h[b*3*NH + 512 + n]  = sH * (256.0f * (float)h0h[last] + (float)h0l[last]);
    out_h[b*3*NH + 1024 + n] = sH * (256.0f * (float)h1h[last] + (float)h1l[last]);
}

// ---------------- int8x2 MMA GEMM with fused GRU epilogue ----------------
// C = sA*sB[n]*(65536*acc_hh + 256*acc_mid), acc exact int32.
// EPI 1: z = sigmoid(v + bias + hterm[b])    -> fp32 plane
// EPI 2: r = sigmoid(v + bias + hterm[b]); r*hv -> int8x2 planes
// EPI 3: v + bias                             -> fp32
// EPI 4: g = tanh(v + ag); z*hv + (1-z)*g     -> int8x2 planes
struct GP {
    const int8_t *Ahi, *Alo, *Bhi, *Blo;
    const float *sA, *sBv;
    float* Cf;
    int8_t *Chi, *Clo;
    const float *bias, *hterm, *h0c;
    const int8_t *hvhi, *hvlo;
    const float *sHv, *inv;
    const float *zb, *agb;
};

template<int EPI>
__global__ void __launch_bounds__(512, 1) gemm_i8(const GP p) {
    extern __shared__ char smem_raw[];
    const uint32_t base = smem_u32(smem_raw);
    const int tid = threadIdx.x;
    const int lane = tid & 31;
    const int w = tid >> 5;
    const int wr = w >> 2;          // 0..3 (32 rows)
    const int wc = w & 3;           // 0..3 (32 cols)
    const int bm = blockIdx.y * BM;
    const int bn = blockIdx.x * BN;

    int c0[2][4][4], c1[2][4][4];
    #pragma unroll
    for (int i = 0; i < 2; i++)
        #pragma unroll
        for (int j = 0; j < 4; j++)
            #pragma unroll
            for (int e = 0; e < 4; e++) { c0[i][j][e] = 0; c1[i][j][e] = 0; }

    // ldmatrix lane offsets (SW64: xor (row*8)&0x30, invariant under +16 rows)
    const int a_row = wr*32 + ((lane>>3)&1)*8 + (lane&7);
    const uint32_t a_lm = a_row*ROWB + ((((uint32_t)(lane>>4))*16) ^ (((uint32_t)a_row<<3)&0x30));
    const int b_row = wc*32 + (lane>>4)*8 + (lane&7);
    const uint32_t b_lm = b_row*ROWB + (((((uint32_t)(lane>>3))&1)*16) ^ (((uint32_t)b_row<<3)&0x30));

    // copy: 4 tiles x 128 rows x 4 16B-chunks = 2048 chunks, 512 thr -> 4/thr
    const int crow = tid >> 2;          // 0..127
    const int ccs  = (tid & 3) * 16;    // byte col in row
    const uint32_t cdc = (uint32_t)ccs ^ (((uint32_t)crow<<3)&0x30);
    auto issue = [&](int s) {
        const int kk = s * KCH + ccs;   // int8 elem col == byte col
        const uint32_t sb = base + (s & (NSLOT-1)) * SLOT;
        const uint32_t so = crow * ROWB + cdc;
        const size_t ga = (size_t)(bm + crow) * 512 + kk;
        const size_t gb = (size_t)(bn + crow) * 512 + kk;
        cp_async16(sb + A_HI_OFF + so, p.Ahi + ga);
        cp_async16(sb + A_LO_OFF + so, p.Alo + ga);
        cp_async16(sb + B_HI_OFF + so, p.Bhi + gb);
        cp_async16(sb + B_LO_OFF + so, p.Blo + gb);
    };

    issue(0); cp_commit();
    issue(1); cp_commit();
    issue(2); cp_commit();

    for (int s = 0; s < NSUP; s++) {
        if (s < NSUP-2) cp_wait<2>(); else if (s == NSUP-2) cp_wait<1>(); else cp_wait<0>();
        __syncthreads();
        if (s + 3 < NSUP) { issue(s + 3); cp_commit(); }

        const uint32_t sb = base + (s & (NSLOT-1)) * SLOT;
        #pragma unroll
        for (int ks = 0; ks < 2; ks++) {
            const uint32_t kx = (uint32_t)ks << 5;
            uint32_t ah[2][4], bh[4][2];
            #pragma unroll
            for (int mt = 0; mt < 2; mt++)
                ldmatrix4(ah[mt][0], ah[mt][1], ah[mt][2], ah[mt][3],
                          (sb + A_HI_OFF + a_lm + mt * (16*ROWB)) ^ kx);
            #pragma unroll
            for (int np = 0; np < 2; np++) {
                uint32_t r0, r1, r2, r3;
                ldmatrix4(r0, r1, r2, r3, (sb + B_HI_OFF + b_lm + np * (16*ROWB)) ^ kx);
                bh[np*2][0] = r0;   bh[np*2][1] = r1;
                bh[np*2+1][0] = r2; bh[np*2+1][1] = r3;
            }
            #pragma unroll
            for (int mt = 0; mt < 2; mt++)
                #pragma unroll
                for (int nt = 0; nt < 4; nt++)
                    mma_s8(c0[mt][nt], ah[mt], bh[nt]);
            {   // hl: Ahi x Blo -> mid
                uint32_t bl[4][2];
                #pragma unroll
                for (int np = 0; np < 2; np++) {
                    uint32_t r0, r1, r2, r3;
                    ldmatrix4(r0, r1, r2, r3, (sb + B_LO_OFF + b_lm + np * (16*ROWB)) ^ kx);
                    bl[np*2][0] = r0;   bl[np*2][1] = r1;
                    bl[np*2+1][0] = r2; bl[np*2+1][1] = r3;
                }
                #pragma unroll
                for (int mt = 0; mt < 2; mt++)
                    #pragma unroll
                    for (int nt = 0; nt < 4; nt++)
                        mma_s8(c1[mt][nt], ah[mt], bl[nt]);
            }
            {   // lh: Alo x Bhi -> mid
                uint32_t al[2][4];
                #pragma unroll
                for (int mt = 0; mt < 2; mt++)
                    ldmatrix4(al[mt][0], al[mt][1], al[mt][2], al[mt][3],
                              (sb + A_LO_OFF + a_lm + mt * (16*ROWB)) ^ kx);
                #pragma unroll
                for (int mt = 0; mt < 2; mt++)
                    #pragma unroll
                    for (int nt = 0; nt < 4; nt++)
                        mma_s8(c1[mt][nt], al[mt], bh[nt]);
            }
        }
    }

    // ---- fused epilogue ----
    const int rbase = bm + wr * 32;
    const int cbase = bn + wc * 32;
    const float sA = p.sA[0];
    #pragma unroll
    for (int mt = 0; mt < 2; mt++) {
        #pragma unroll
        for (int er = 0; er < 2; er++) {
            const int gm = rbase + mt*16 + (lane >> 2) + er*8;
            const int bb = gm >> 10;
            #pragma unroll
            for (int nt = 0; nt < 4; nt++) {
                #pragma unroll
                for (int ec = 0; ec < 2; ec++) {
                    const int gn = cbase + nt*8 + (lane & 3)*2 + ec;
                    const size_t idx = (size_t)gm * NN + gn;
                    const int e = er*2 + ec;
                    float val = sA * p.sBv[gn] *
                        (65536.0f * (float)c0[mt][nt][e] + 256.0f * (float)c1[mt][nt][e]);
                    if (EPI == 1) {
                        val += p.bias[gn];
                        if (p.hterm) val += p.hterm[bb * NH + gn];
                        p.Cf[idx] = 1.f / (1.f + __expf(-val));
                    } else if (EPI == 2) {
                        val += p.bias[gn];
                        if (p.hterm) val += p.hterm[bb * NH + gn];
                        float r_ = 1.f / (1.f + __expf(-val));
                        float hv = p.h0c ? p.h0c[bb * NH + gn]
                            : p.sHv[0] * (256.0f * (float)p.hvhi[idx] + (float)p.hvlo[idx]);
                        quant16(r_ * hv, p.inv[0], &p.Chi[idx], &p.Clo[idx]);
                    } else if (EPI == 3) {
                        p.Cf[idx] = val + p.bias[gn];
                    } else {
                        float g = tanhf(val + p.agb[idx]);
                        float z = p.zb[idx];
                        float hv = p.h0c ? p.h0c[bb * NH + gn]
                            : p.sHv[0] * (256.0f * (float)p.hvhi[idx] + (float)p.hvlo[idx]);
                        quant16(z * hv + (1.f - z) * g, p.inv[0], &p.Chi[idx], &p.Clo[idx]);
                    }
                }
            }
        }
    }
}

// ---------------- host ----------------
extern "C" void kernel_launch(void* const* d_in, const int* in_sizes, int n_in,
                              void* d_out, int out_size) {
    const float* input = (const float*)d_in[0];
    const float* hs    = (const float*)d_in[1];
    const float* Wzx   = (const float*)d_in[2];
    const float* bzx   = (const float*)d_in[3];
    const float* Wzh   = (const float*)d_in[4];
    const float* Wrx   = (const float*)d_in[5];
    const float* brx   = (const float*)d_in[6];
    const float* Wrh   = (const float*)d_in[7];
    const float* Wgx   = (const float*)d_in[8];
    const float* bgx   = (const float*)d_in[9];
    const float* Wgh   = (const float*)d_in[10];
    const float* Wout  = (const float*)d_in[11];
    const float* bout  = (const float*)d_in[12];
    float* out = (float*)d_out;

    int8_t *qhi, *qlo, *wqh, *wql;
    float *wtf, *sbv, *z, *ag, *hz, *hr, *h0c, *sc;
    cudaGetSymbolAddress((void**)&qhi, g_qhi);
    cudaGetSymbolAddress((void**)&qlo, g_qlo);
    cudaGetSymbolAddress((void**)&wqh, g_wqh);
    cudaGetSymbolAddress((void**)&wql, g_wql);
    cudaGetSymbolAddress((void**)&wtf, g_wtf);
    cudaGetSymbolAddress((void**)&sbv, g_sbv);
    cudaGetSymbolAddress((void**)&z,   g_z);
    cudaGetSymbolAddress((void**)&ag,  g_ag);
    cudaGetSymbolAddress((void**)&hz,  g_hz);
    cudaGetSymbolAddress((void**)&hr,  g_hr);
    cudaGetSymbolAddress((void**)&h0c, g_h0c);
    cudaGetSymbolAddress((void**)&sc,  g_sc);

    cudaFuncSetAttribute(gemm_i8<1>, cudaFuncAttributeMaxDynamicSharedMemorySize, SMEM_BYTES);
    cudaFuncSetAttribute(gemm_i8<2>, cudaFuncAttributeMaxDynamicSharedMemorySize, SMEM_BYTES);
    cudaFuncSetAttribute(gemm_i8<3>, cudaFuncAttributeMaxDynamicSharedMemorySize, SMEM_BYTES);
    cudaFuncSetAttribute(gemm_i8<4>, cudaFuncAttributeMaxDynamicSharedMemorySize, SMEM_BYTES);

    // ---- prep ----
    k_initmax<<<1, 1>>>();
    k_maxX<<<2048, 256>>>((const float4*)input, PLANE / 4);
    k_maxh0<<<64, 512>>>(hs);
    k_scale<<<1, 1>>>();
    k_quantX<<<2048, 256>>>(input, qhi, qlo);
    k_pre<<<dim3(64, 2), 512>>>(hs, Wzh, Wrh, hz, hr, h0c);
    k_wprep_all<<<dim3(16, 16, 13), dim3(32, 8)>>>(Wzx, Wzh, Wrx, Wrh, Wgx, Wgh, Wout, wtf);
    k_wquant<<<dim3(512, 13), 128>>>(wtf, wqh, wql, sbv);

    const dim3 grid(NN / BN, NM / BM);   // (4, 512)
    const dim3 blk(512);
    int8_t* QH[5]; int8_t* QL[5];
    for (int i = 0; i < 5; i++) { QH[i] = qhi + (size_t)i*PLANE; QL[i] = qlo + (size_t)i*PLANE; }
    const float *sX = sc + 0, *sH = sc + 1, *invH = sc + 3;

    auto run = [&](int epi, int aplane, const float* sa, int wslot,
                   float* cf, int cplane,
                   const float* bias, const float* hterm, const float* h0cp,
                   int hvplane, const float* zb, const float* agb) {
        GP p{};
        p.Ahi = QH[aplane]; p.Alo = QL[aplane];
        p.Bhi = wqh + (size_t)wslot*WSTRIDE; p.Blo = wql + (size_t)wslot*WSTRIDE;
        p.sA = sa; p.sBv = sbv + wslot*512;
        p.Cf = cf;
        p.Chi = cplane >= 0 ? QH[cplane] : nullptr;
        p.Clo = cplane >= 0 ? QL[cplane] : nullptr;
        p.bias = bias; p.hterm = hterm; p.h0c = h0cp;
        p.hvhi = hvplane >= 0 ? QH[hvplane] : nullptr;
        p.hvlo = hvplane >= 0 ? QL[hvplane] : nullptr;
        p.sHv = sH; p.inv = invH;
        p.zb = zb; p.agb = agb;
        if (epi == 1)      gemm_i8<1><<<grid, blk, SMEM_BYTES>>>(p);
        else if (epi == 2) gemm_i8<2><<<grid, blk, SMEM_BYTES>>>(p);
        else if (epi == 3) gemm_i8<3><<<grid, blk, SMEM_BYTES>>>(p);
        else               gemm_i8<4><<<grid, blk, SMEM_BYTES>>>(p);
    };

    // ---- layer 0 (h = const h0; x = plane 0) ----
    run(1, 0, sX, 0,  z,  -1, bzx,      hz,      nullptr, -1, nullptr, nullptr);
    run(2, 0, sX, 1,  nullptr, 1, brx,  hr,      h0c,     -1, nullptr, nullptr);
    run(3, 0, sX, 2,  ag, -1, bgx,      nullptr, nullptr, -1, nullptr, nullptr);
    run(4, 1, sH, 3,  nullptr, 2, nullptr, nullptr, h0c,  -1, z, ag);
    // ---- layer 1 (x == h == plane 2) ----
    run(1, 2, sH, 4,  z,  -1, bzx+512,  nullptr, nullptr, -1, nullptr, nullptr);
    run(2, 2, sH, 5,  nullptr, 1, brx+512, nullptr, nullptr, 2, nullptr, nullptr);
    run(3, 2, sH, 6,  ag, -1, bgx+512,  nullptr, nullptr, -1, nullptr, nullptr);
    run(4, 1, sH, 7,  nullptr, 3, nullptr, nullptr, nullptr, 2, z, ag);
    // ---- layer 2 (x == h == plane 3) ----
    run(1, 3, sH, 8,  z,  -1, bzx+1024, nullptr, nullptr, -1, nullptr, nullptr);
    run(2, 3, sH, 9,  nullptr, 1, brx+1024, nullptr, nullptr, 3, nullptr, nullptr);
    run(3, 3, sH, 10, ag, -1, bgx+1024, nullptr, nullptr, -1, nullptr, nullptr);
    run(4, 1, sH, 11, nullptr, 4, nullptr, nullptr, nullptr, 3, z, ag);
    // ---- output projection ----
    run(3, 4, sH, 12, out, -1, bout,    nullptr, nullptr, -1, nullptr, nullptr);

    k_tail<<<64, 512>>>(hs, QH[2], QL[2], QH[3], QL[3], out + PLANE);
}